// round 12
// baseline (speedup 1.0000x reference)
#include <cuda_runtime.h>
#include <math.h>
#include <stdint.h>

#define BB 4
#define CC 64
#define NN 4096
#define KK 256
#define PP 256
#define NTILE 32            // 4096 / 128
#define NPAIRS 528          // 32*33/2 upper-triangle tiles

// Scratch (no allocs allowed) ------------------------------------------------
__device__ float g_diag[BB][NN];            // o_i = ||x_i||^2
__device__ float g_pz[BB][NTILE][NN];       // partial Z (additive, by slot)
__device__ float g_pt[BB][NTILE][NN];       // partial T = sum (s-o)e^(s-o)
__device__ float g_iZ[BB][NN];              // 1/Z per row (from sort pass)
__device__ int   g_sel[BB * KK];            // selected row indices (sorted)
__device__ float g_samp32[32][BB * KK * CC];// j-slab partials of sampled

// ---------------------------------------------------------------------------
// Pass 0: diagonal o_i = sum_c x^2. grid (4, BB), 1024 threads.
// ---------------------------------------------------------------------------
__global__ void diag_kernel(const float* __restrict__ L) {
    const int b = blockIdx.y;
    const int i = blockIdx.x * 1024 + threadIdx.x;
    const float* Lb = L + (size_t)b * CC * NN;
    float acc = 0.f;
#pragma unroll 8
    for (int c = 0; c < CC; c++) {
        float v = Lb[(size_t)c * NN + i];
        acc += v * v;
    }
    g_diag[b][i] = acc;
}

// ---------------------------------------------------------------------------
// Pass 1: symmetric-tile softmax stats with fixed diag offsets (additive).
// One block per (it<=jt) 128x128 tile. grid (528, BB), 256 threads.
// Row (Z,T) -> slot jt; col (transpose) (Z,T) -> slot it (skipped on diagonal).
// ---------------------------------------------------------------------------
__global__ void __launch_bounds__(256, 3)
entropy_kernel(const float* __restrict__ L) {
    __shared__ __align__(16) float Xi[64 * 128];  // 32 KB [c][ii]
    __shared__ __align__(16) float Xj[64 * 64];   // 16 KB [c][jj] + scratch

    // decode upper-triangle pair
    int rem = blockIdx.x, it = 0;
    while (rem >= NTILE - it) { rem -= NTILE - it; it++; }
    const int jt = it + rem;

    const int b = blockIdx.y;
    const int t = threadIdx.x;
    const int tx = t & 15, ty = t >> 4;
    const int i0 = it * 128, j0 = jt * 128;
    const float* Lb = L + (size_t)b * CC * NN;
    const bool offdiag = (it != jt);

    for (int idx = t; idx < 2048; idx += 256) {          // 64*128 floats /4
        int c = idx >> 5, q = idx & 31;
        ((float4*)Xi)[c * 32 + q] = ((const float4*)(Lb + (size_t)c * NN + i0))[q];
    }

    float oi[8];
    {
        float4 o0 = *(const float4*)&g_diag[b][i0 + ty * 8];
        float4 o1 = *(const float4*)&g_diag[b][i0 + ty * 8 + 4];
        oi[0] = o0.x; oi[1] = o0.y; oi[2] = o0.z; oi[3] = o0.w;
        oi[4] = o1.x; oi[5] = o1.y; oi[6] = o1.z; oi[7] = o1.w;
    }

    float z[8], tq[8];
#pragma unroll
    for (int u = 0; u < 8; u++) { z[u] = 0.f; tq[u] = 0.f; }

    for (int h = 0; h < 2; h++) {
        __syncthreads();
        for (int idx = t; idx < 1024; idx += 256) {      // 64*64 /4
            int c = idx >> 4, q = idx & 15;
            ((float4*)Xj)[c * 16 + q] =
                ((const float4*)(Lb + (size_t)c * NN + j0 + h * 64))[q];
        }
        __syncthreads();

        float acc[8][4];
#pragma unroll
        for (int u = 0; u < 8; u++)
#pragma unroll
            for (int v = 0; v < 4; v++) acc[u][v] = 0.f;

#pragma unroll 8
        for (int c = 0; c < 64; c++) {
            float4 a0 = *(const float4*)&Xi[c * 128 + ty * 8];
            float4 a1 = *(const float4*)&Xi[c * 128 + ty * 8 + 4];
            float4 bv = *(const float4*)&Xj[c * 64 + tx * 4];
            float a[8] = {a0.x, a0.y, a0.z, a0.w, a1.x, a1.y, a1.z, a1.w};
            float bb[4] = {bv.x, bv.y, bv.z, bv.w};
#pragma unroll
            for (int u = 0; u < 8; u++)
#pragma unroll
                for (int v = 0; v < 4; v++) acc[u][v] += a[u] * bb[v];
        }

        // row side: additive (Z, T) with fixed offset oi[u]
#pragma unroll
        for (int u = 0; u < 8; u++)
#pragma unroll
            for (int v = 0; v < 4; v++) {
                float s = acc[u][v] - oi[u];
                float e = __expf(s);
                z[u] += e; tq[u] += s * e;
            }

        // col (transpose) side: offsets o_j, reduce over u then over ty
        if (offdiag) {
            float4 ojv = *(const float4*)&g_diag[b][j0 + h * 64 + tx * 4];
            float oj[4] = {ojv.x, ojv.y, ojv.z, ojv.w};
            __syncthreads();                 // done reading Xj; reuse as scratch
            float* scz = Xj;                 // [16][64]
            float* sct = Xj + 1024;
#pragma unroll
            for (int v = 0; v < 4; v++) {
                float zc = 0.f, tc = 0.f;
#pragma unroll
                for (int u = 0; u < 8; u++) {
                    float s = acc[u][v] - oj[v];
                    float e = __expf(s);
                    zc += e; tc += s * e;
                }
                int cl = tx * 4 + v;
                scz[ty * 64 + cl] = zc; sct[ty * 64 + cl] = tc;
            }
            __syncthreads();
            if (t < 64) {
                float Z = 0.f, T = 0.f;
#pragma unroll 4
                for (int g = 0; g < 16; g++) {
                    Z += scz[g * 64 + t];
                    T += sct[g * 64 + t];
                }
                int row = j0 + h * 64 + t;
                g_pz[b][it][row] = Z; g_pt[b][it][row] = T;
            }
        }
    }

    // row merge across tx: plain shuffle adds over 16 lanes, write slot jt
#pragma unroll
    for (int u = 0; u < 8; u++) {
        float Z = z[u], T = tq[u];
#pragma unroll
        for (int d = 8; d >= 1; d >>= 1) {
            Z += __shfl_xor_sync(0xffffffff, Z, d);
            T += __shfl_xor_sync(0xffffffff, T, d);
        }
        if (tx == 0) {
            int row = i0 + ty * 8 + u;
            g_pz[b][jt][row] = Z; g_pt[b][jt][row] = T;
        }
    }
}

// ---------------------------------------------------------------------------
// Pass 2: sum 32 slot-partials -> entropy + 1/Z, then per-batch bitonic
// argsort on packed u64 (orderable float bits << 32 | idx) == stable argsort.
// 4 blocks x 1024 threads.
// ---------------------------------------------------------------------------
__global__ void sort_kernel(float* __restrict__ out_idx) {
    __shared__ unsigned long long kv[NN];
    const int b = blockIdx.x, t = threadIdx.x;
    for (int i = t; i < NN; i += 1024) {
        float Z = 0.f, T = 0.f;
#pragma unroll 8
        for (int s = 0; s < NTILE; s++) {
            Z += g_pz[b][s][i];
            T += g_pt[b][s][i];
        }
        float key = logf(Z) - T / Z;
        g_iZ[b][i] = 1.f / Z;
        unsigned int kb = __float_as_uint(key);
        kb = (kb & 0x80000000u) ? ~kb : (kb | 0x80000000u);
        kv[i] = ((unsigned long long)kb << 32) | (unsigned int)i;
    }
    __syncthreads();
    for (int k = 2; k <= NN; k <<= 1) {
        for (int j = k >> 1; j > 0; j >>= 1) {
            for (int i = t; i < NN; i += 1024) {
                int ixj = i ^ j;
                if (ixj > i) {
                    bool up = ((i & k) == 0);
                    unsigned long long a = kv[i], c = kv[ixj];
                    if ((a > c) == up) { kv[i] = c; kv[ixj] = a; }
                }
            }
            __syncthreads();
        }
    }
    if (t < KK) {
        int v = (int)(kv[t] & 0xffffffffu);
        g_sel[b * KK + t] = v;
        out_idx[b * KK + t] = (float)v;
    }
}

// ---------------------------------------------------------------------------
// Pass 3a: attn = exp(s - o_k) / Z for selected rows (final, normalized).
// grid (4 ktiles, 32 jslabs, B) = 512 blocks, 256 threads.
// Block: 64 sel-rows x 128 j. Thread: 4k x 8j tile (1+2 LDS.128 : 32 FFMA).
// smem = exactly 48 KB; sel/diag/iZ come straight from L1-cached gmem.
// ---------------------------------------------------------------------------
__global__ void __launch_bounds__(256) scores_kernel(const float* __restrict__ L,
                                                     float* __restrict__ attn) {
    __shared__ __align__(16) float Xi[64 * 64];    // [c][k] 16 KB
    __shared__ __align__(16) float Xj[64 * 128];   // [c][j] 32 KB
    const int b  = blockIdx.z;
    const int k0 = blockIdx.x * 64;
    const int jbase = blockIdx.y * 128;
    const int t  = threadIdx.x;
    const int j8 = (t & 15) * 8, k4 = (t >> 4) * 4;
    const float* Lb = L + (size_t)b * CC * NN;
    const int* selp = g_sel + b * KK + k0;

    for (int idx = t; idx < 4096; idx += 256) {
        int c = idx >> 6, k = idx & 63;
        Xi[c * 64 + k] = Lb[(size_t)c * NN + selp[k]];
    }
    for (int idx = t; idx < 2048; idx += 256) {   // 64*128 /4 float4s
        int c = idx >> 5, q = idx & 31;
        ((float4*)Xj)[c * 32 + q] =
            ((const float4*)(Lb + (size_t)c * NN + jbase))[q];
    }
    __syncthreads();

    float acc[4][8];
#pragma unroll
    for (int i = 0; i < 4; i++)
#pragma unroll
        for (int j = 0; j < 8; j++) acc[i][j] = 0.f;

#pragma unroll 8
    for (int c = 0; c < 64; c++) {
        float4 a4 = *(const float4*)&Xi[c * 64 + k4];
        float4 b0 = *(const float4*)&Xj[c * 128 + j8];
        float4 b1 = *(const float4*)&Xj[c * 128 + j8 + 4];
        float a[4] = {a4.x, a4.y, a4.z, a4.w};
        float bb[8] = {b0.x, b0.y, b0.z, b0.w, b1.x, b1.y, b1.z, b1.w};
#pragma unroll
        for (int i = 0; i < 4; i++)
#pragma unroll
            for (int j = 0; j < 8; j++) acc[i][j] += a[i] * bb[j];
    }

#pragma unroll
    for (int i = 0; i < 4; i++) {
        int col = selp[k4 + i];
        float o  = g_diag[b][col];
        float iz = g_iZ[b][col];
        float4 r0, r1;
        r0.x = __expf(acc[i][0] - o) * iz;
        r0.y = __expf(acc[i][1] - o) * iz;
        r0.z = __expf(acc[i][2] - o) * iz;
        r0.w = __expf(acc[i][3] - o) * iz;
        r1.x = __expf(acc[i][4] - o) * iz;
        r1.y = __expf(acc[i][5] - o) * iz;
        r1.z = __expf(acc[i][6] - o) * iz;
        r1.w = __expf(acc[i][7] - o) * iz;
        float* dst = attn + ((size_t)b * KK + k0 + k4 + i) * NN + jbase + j8;
        *(float4*)dst       = r0;
        *(float4*)(dst + 4) = r1;
    }
}

// ---------------------------------------------------------------------------
// Pass 3b: partial sampled over one j-slab (128 j) — block 128 k x 64 c.
// grid (2 ktiles, 32 jslabs, B) = 256 blocks, 256 threads.
// Thread: 8k x 4c tile (2+1 LDS.128 : 32 FFMA). attn staged transposed.
// ---------------------------------------------------------------------------
#define ATP 136   // At row pad ([jj][k]): 136*4 = 544 B, 16B-aligned rows
#define XTP 68    // XT row pad ([jj][c]): 272 B, 16B-aligned

__global__ void __launch_bounds__(256) sampled_kernel(const float* __restrict__ L,
                                                      const float* __restrict__ attn) {
    __shared__ __align__(16) float At[32 * ATP];   // 17.4 KB
    __shared__ __align__(16) float XT[32 * XTP];   // 8.7 KB
    const int b  = blockIdx.z;
    const int k0 = blockIdx.x * 128;
    const int jbase = blockIdx.y * 128;
    const int t  = threadIdx.x;
    const int k8 = (t >> 4) * 8, c4 = (t & 15) * 4;
    const float* Lb = L + (size_t)b * CC * NN;

    float acc[8][4];
#pragma unroll
    for (int i = 0; i < 8; i++)
#pragma unroll
        for (int j = 0; j < 4; j++) acc[i][j] = 0.f;

    for (int jst = 0; jst < 4; jst++) {
        __syncthreads();
        // stage At[jj][k]: 128 k x 32 j, coalesced float4 reads along j
        for (int idx = t; idx < 1024; idx += 256) {
            int kk = idx >> 3, jq = idx & 7;
            float4 v = *(const float4*)(attn + ((size_t)b * KK + k0 + kk) * NN
                                        + jbase + jst * 32 + jq * 4);
            At[(jq * 4 + 0) * ATP + kk] = v.x;
            At[(jq * 4 + 1) * ATP + kk] = v.y;
            At[(jq * 4 + 2) * ATP + kk] = v.z;
            At[(jq * 4 + 3) * ATP + kk] = v.w;
        }
        // stage XT[jj][c]: 64 c x 32 j
        for (int idx = t; idx < 512; idx += 256) {
            int c = idx >> 3, jq = idx & 7;
            float4 v = *(const float4*)(Lb + (size_t)c * NN
                                        + jbase + jst * 32 + jq * 4);
            XT[(jq * 4 + 0) * XTP + c] = v.x;
            XT[(jq * 4 + 1) * XTP + c] = v.y;
            XT[(jq * 4 + 2) * XTP + c] = v.z;
            XT[(jq * 4 + 3) * XTP + c] = v.w;
        }
        __syncthreads();

#pragma unroll 8
        for (int jj = 0; jj < 32; jj++) {
            float4 p0 = *(const float4*)&At[jj * ATP + k8];
            float4 p1 = *(const float4*)&At[jj * ATP + k8 + 4];
            float4 x4 = *(const float4*)&XT[jj * XTP + c4];
            float p[8] = {p0.x, p0.y, p0.z, p0.w, p1.x, p1.y, p1.z, p1.w};
            float x[4] = {x4.x, x4.y, x4.z, x4.w};
#pragma unroll
            for (int i = 0; i < 8; i++)
#pragma unroll
                for (int j = 0; j < 4; j++) acc[i][j] += p[i] * x[j];
        }
    }
    int q = blockIdx.y;
#pragma unroll
    for (int i = 0; i < 8; i++)
        *(float4*)&g_samp32[q][((size_t)b * KK + k0 + k8 + i) * CC + c4] =
            make_float4(acc[i][0], acc[i][1], acc[i][2], acc[i][3]);
}

// ---------------------------------------------------------------------------
// Pass 4: MLP + L2 normalize, 8 rows per block. 128 blocks x 256 threads.
// ---------------------------------------------------------------------------
__global__ void mlp_kernel(const float* __restrict__ w1, const float* __restrict__ b1,
                           const float* __restrict__ w2, const float* __restrict__ b2,
                           float* __restrict__ emb) {
    __shared__ float s[8 * 64];
    __shared__ float h[8 * 256];
    __shared__ float red[256];
    const int R0 = blockIdx.x * 8;
    const int t = threadIdx.x;

    for (int idx = t; idx < 8 * 64; idx += 256) {
        int r = idx >> 6, c = idx & 63;
        size_t off = (size_t)(R0 + r) * CC + c;
        float acc = 0.f;
#pragma unroll
        for (int q = 0; q < 32; q++) acc += g_samp32[q][off];
        s[r * 64 + c] = acc;
    }
    __syncthreads();

    float a1[8];
#pragma unroll
    for (int r = 0; r < 8; r++) a1[r] = b1[t];
#pragma unroll 4
    for (int c = 0; c < CC; c++) {
        float wv = w1[c * PP + t];
#pragma unroll
        for (int r = 0; r < 8; r++) a1[r] += s[r * 64 + c] * wv;
    }
#pragma unroll
    for (int r = 0; r < 8; r++) h[r * 256 + t] = fmaxf(a1[r], 0.f);
    __syncthreads();

    float a2[8];
#pragma unroll
    for (int r = 0; r < 8; r++) a2[r] = b2[t];
#pragma unroll 4
    for (int p2 = 0; p2 < PP; p2++) {
        float wv = w2[p2 * PP + t];
#pragma unroll
        for (int r = 0; r < 8; r++) a2[r] += h[r * 256 + p2] * wv;
    }

    for (int r = 0; r < 8; r++) {
        red[t] = a2[r] * a2[r];
        __syncthreads();
        for (int sd = 128; sd > 0; sd >>= 1) { if (t < sd) red[t] += red[t + sd]; __syncthreads(); }
        float denom = fmaxf(sqrtf(red[0]), 1e-12f);
        __syncthreads();
        emb[(size_t)(R0 + r) * PP + t] = a2[r] / denom;
    }
}

// ---------------------------------------------------------------------------
extern "C" void kernel_launch(void* const* d_in, const int* in_sizes, int n_in,
                              void* d_out, int out_size) {
    const float* L  = (const float*)d_in[0];
    const float* w1 = (const float*)d_in[1];
    const float* b1 = (const float*)d_in[2];
    const float* w2 = (const float*)d_in[3];
    const float* b2 = (const float*)d_in[4];

    float* out  = (float*)d_out;
    float* emb  = out;                                   // [B,K,P]
    float* attn = out + (size_t)BB * KK * PP;            // [B,K,N]
    float* oidx = attn + (size_t)BB * KK * NN;           // [B,K]

    diag_kernel<<<dim3(4, BB), 1024>>>(L);
    entropy_kernel<<<dim3(NPAIRS, BB), 256>>>(L);
    sort_kernel<<<BB, 1024>>>(oidx);
    scores_kernel<<<dim3(4, 32, BB), 256>>>(L, attn);
    sampled_kernel<<<dim3(2, 32, BB), 256>>>(L, attn);
    mlp_kernel<<<128, 256>>>(w1, b1, w2, b2, emb);
}

// round 13
// speedup vs baseline: 1.0408x; 1.0408x over previous
#include <cuda_runtime.h>
#include <math.h>
#include <stdint.h>

#define BB 4
#define CC 64
#define NN 4096
#define KK 256
#define PP 256
#define NTILE 32            // 4096 / 128
#define NPAIRS 528          // 32*33/2 upper-triangle tiles

// Scratch (no allocs allowed) ------------------------------------------------
__device__ float g_diag[BB][NN];            // o_i = ||x_i||^2
__device__ float g_pz[BB][NTILE][NN];       // partial Z (additive, by slot)
__device__ float g_pt[BB][NTILE][NN];       // partial T = sum (s-o)e^(s-o)
__device__ float g_iZ[BB][NN];              // 1/Z per row (from sort pass)
__device__ int   g_sel[BB * KK];            // selected row indices (sorted)
__device__ float g_Xsel[BB][CC][KK];        // gathered selected columns, c-major
__device__ float g_osel[BB][KK];            // gathered diag offsets
__device__ float g_izsel[BB][KK];           // gathered 1/Z
__device__ float g_samp32[32][BB * KK * CC];// j-slab partials of sampled

// ---------------------------------------------------------------------------
// Pass 0: diagonal o_i = sum_c x^2. grid (4, BB), 1024 threads.
// ---------------------------------------------------------------------------
__global__ void diag_kernel(const float* __restrict__ L) {
    const int b = blockIdx.y;
    const int i = blockIdx.x * 1024 + threadIdx.x;
    const float* Lb = L + (size_t)b * CC * NN;
    float acc = 0.f;
#pragma unroll 8
    for (int c = 0; c < CC; c++) {
        float v = Lb[(size_t)c * NN + i];
        acc += v * v;
    }
    g_diag[b][i] = acc;
}

// ---------------------------------------------------------------------------
// Pass 1: symmetric-tile softmax stats with fixed diag offsets (additive).
// One block per (it<=jt) 128x128 tile. grid (528, BB), 256 threads.
// Row (Z,T) -> slot jt; col (transpose) (Z,T) -> slot it (skipped on diagonal).
// ---------------------------------------------------------------------------
__global__ void __launch_bounds__(256, 3)
entropy_kernel(const float* __restrict__ L) {
    __shared__ __align__(16) float Xi[64 * 128];  // 32 KB [c][ii]
    __shared__ __align__(16) float Xj[64 * 64];   // 16 KB [c][jj] + scratch

    // decode upper-triangle pair
    int rem = blockIdx.x, it = 0;
    while (rem >= NTILE - it) { rem -= NTILE - it; it++; }
    const int jt = it + rem;

    const int b = blockIdx.y;
    const int t = threadIdx.x;
    const int tx = t & 15, ty = t >> 4;
    const int i0 = it * 128, j0 = jt * 128;
    const float* Lb = L + (size_t)b * CC * NN;
    const bool offdiag = (it != jt);

    for (int idx = t; idx < 2048; idx += 256) {          // 64*128 floats /4
        int c = idx >> 5, q = idx & 31;
        ((float4*)Xi)[c * 32 + q] = ((const float4*)(Lb + (size_t)c * NN + i0))[q];
    }

    float oi[8];
    {
        float4 o0 = *(const float4*)&g_diag[b][i0 + ty * 8];
        float4 o1 = *(const float4*)&g_diag[b][i0 + ty * 8 + 4];
        oi[0] = o0.x; oi[1] = o0.y; oi[2] = o0.z; oi[3] = o0.w;
        oi[4] = o1.x; oi[5] = o1.y; oi[6] = o1.z; oi[7] = o1.w;
    }

    float z[8], tq[8];
#pragma unroll
    for (int u = 0; u < 8; u++) { z[u] = 0.f; tq[u] = 0.f; }

    for (int h = 0; h < 2; h++) {
        __syncthreads();
        for (int idx = t; idx < 1024; idx += 256) {      // 64*64 /4
            int c = idx >> 4, q = idx & 15;
            ((float4*)Xj)[c * 16 + q] =
                ((const float4*)(Lb + (size_t)c * NN + j0 + h * 64))[q];
        }
        __syncthreads();

        float acc[8][4];
#pragma unroll
        for (int u = 0; u < 8; u++)
#pragma unroll
            for (int v = 0; v < 4; v++) acc[u][v] = 0.f;

#pragma unroll 8
        for (int c = 0; c < 64; c++) {
            float4 a0 = *(const float4*)&Xi[c * 128 + ty * 8];
            float4 a1 = *(const float4*)&Xi[c * 128 + ty * 8 + 4];
            float4 bv = *(const float4*)&Xj[c * 64 + tx * 4];
            float a[8] = {a0.x, a0.y, a0.z, a0.w, a1.x, a1.y, a1.z, a1.w};
            float bb[4] = {bv.x, bv.y, bv.z, bv.w};
#pragma unroll
            for (int u = 0; u < 8; u++)
#pragma unroll
                for (int v = 0; v < 4; v++) acc[u][v] += a[u] * bb[v];
        }

        // row side: additive (Z, T) with fixed offset oi[u]
#pragma unroll
        for (int u = 0; u < 8; u++)
#pragma unroll
            for (int v = 0; v < 4; v++) {
                float s = acc[u][v] - oi[u];
                float e = __expf(s);
                z[u] += e; tq[u] += s * e;
            }

        // col (transpose) side: offsets o_j, reduce over u then over ty
        if (offdiag) {
            float4 ojv = *(const float4*)&g_diag[b][j0 + h * 64 + tx * 4];
            float oj[4] = {ojv.x, ojv.y, ojv.z, ojv.w};
            __syncthreads();                 // done reading Xj; reuse as scratch
            float* scz = Xj;                 // [16][64]
            float* sct = Xj + 1024;
#pragma unroll
            for (int v = 0; v < 4; v++) {
                float zc = 0.f, tc = 0.f;
#pragma unroll
                for (int u = 0; u < 8; u++) {
                    float s = acc[u][v] - oj[v];
                    float e = __expf(s);
                    zc += e; tc += s * e;
                }
                int cl = tx * 4 + v;
                scz[ty * 64 + cl] = zc; sct[ty * 64 + cl] = tc;
            }
            __syncthreads();
            if (t < 64) {
                float Z = 0.f, T = 0.f;
#pragma unroll 4
                for (int g = 0; g < 16; g++) {
                    Z += scz[g * 64 + t];
                    T += sct[g * 64 + t];
                }
                int row = j0 + h * 64 + t;
                g_pz[b][it][row] = Z; g_pt[b][it][row] = T;
            }
        }
    }

    // row merge across tx: plain shuffle adds over 16 lanes, write slot jt
#pragma unroll
    for (int u = 0; u < 8; u++) {
        float Z = z[u], T = tq[u];
#pragma unroll
        for (int d = 8; d >= 1; d >>= 1) {
            Z += __shfl_xor_sync(0xffffffff, Z, d);
            T += __shfl_xor_sync(0xffffffff, T, d);
        }
        if (tx == 0) {
            int row = i0 + ty * 8 + u;
            g_pz[b][jt][row] = Z; g_pt[b][jt][row] = T;
        }
    }
}

// ---------------------------------------------------------------------------
// Pass 2: sum 32 slot-partials -> entropy + 1/Z, bitonic argsort on packed
// u64, then TAIL: gather selected columns into compact g_Xsel (+ o, iZ).
// 4 blocks x 1024 threads.
// ---------------------------------------------------------------------------
__global__ void sort_kernel(const float* __restrict__ L, float* __restrict__ out_idx) {
    __shared__ unsigned long long kv[NN];
    const int b = blockIdx.x, t = threadIdx.x;
    for (int i = t; i < NN; i += 1024) {
        float Z = 0.f, T = 0.f;
#pragma unroll 8
        for (int s = 0; s < NTILE; s++) {
            Z += g_pz[b][s][i];
            T += g_pt[b][s][i];
        }
        float key = logf(Z) - T / Z;
        g_iZ[b][i] = 1.f / Z;
        unsigned int kb = __float_as_uint(key);
        kb = (kb & 0x80000000u) ? ~kb : (kb | 0x80000000u);
        kv[i] = ((unsigned long long)kb << 32) | (unsigned int)i;
    }
    __syncthreads();
    for (int k = 2; k <= NN; k <<= 1) {
        for (int j = k >> 1; j > 0; j >>= 1) {
            for (int i = t; i < NN; i += 1024) {
                int ixj = i ^ j;
                if (ixj > i) {
                    bool up = ((i & k) == 0);
                    unsigned long long a = kv[i], c = kv[ixj];
                    if ((a > c) == up) { kv[i] = c; kv[ixj] = a; }
                }
            }
            __syncthreads();
        }
    }
    if (t < KK) {
        int v = (int)(kv[t] & 0xffffffffu);
        g_sel[b * KK + t] = v;
        out_idx[b * KK + t] = (float)v;
        g_osel[b][t]  = g_diag[b][v];
        g_izsel[b][t] = g_iZ[b][v];
    }
    __syncthreads();
    // gather tail: g_Xsel[b][c][k] = X[b][c][sel[k]] (writes coalesced)
    const float* Lb = L + (size_t)b * CC * NN;
    for (int idx = t; idx < CC * KK; idx += 1024) {
        int c = idx >> 8, k = idx & 255;
        int col = (int)(kv[k] & 0xffffffffu);
        g_Xsel[b][c][k] = Lb[(size_t)c * NN + col];
    }
}

// ---------------------------------------------------------------------------
// Pass 3a: attn = exp(s - o_k) / Z for selected rows (final, normalized).
// grid (4 ktiles, 32 jslabs, B) = 512 blocks, 256 threads. Block: 64 sel-rows
// x 128 cols (2 inner j-tiles of 64). Thread: 4x4 tile, LDS.128 both operands.
// Xi staged COALESCED from pre-gathered g_Xsel.
// ---------------------------------------------------------------------------
__global__ void scores_kernel(const float* __restrict__ L, float* __restrict__ attn) {
    __shared__ __align__(16) float Xi[64 * 64];   // [c][r] 16 KB
    __shared__ __align__(16) float Xj[64 * 64];   // [c][j] 16 KB
    __shared__ float Ob[64], Zb[64];
    const int b  = blockIdx.z;
    const int k0 = blockIdx.x * 64;
    const int jslab = blockIdx.y * 128;
    const int t  = threadIdx.x;
    const int r4 = (t & 15) * 4, c4 = (t >> 4) * 4;
    const float* Lb = L + (size_t)b * CC * NN;

    for (int idx = t; idx < 1024; idx += 256) {   // 64c x 64k /4, coalesced
        int c = idx >> 4, q = idx & 15;
        ((float4*)Xi)[c * 16 + q] = ((const float4*)&g_Xsel[b][c][k0])[q];
    }
    if (t < 64) {
        Ob[t] = g_osel[b][k0 + t];
        Zb[t] = g_izsel[b][k0 + t];
    }

    for (int jt = 0; jt < 2; jt++) {
        __syncthreads();
        for (int idx = t; idx < 1024; idx += 256) {   // 64*64 /4 float4s
            int c = idx >> 4, q = idx & 15;
            ((float4*)Xj)[c * 16 + q] =
                ((const float4*)(Lb + (size_t)c * NN + jslab + jt * 64))[q];
        }
        __syncthreads();

        float acc[4][4];
#pragma unroll
        for (int i = 0; i < 4; i++)
#pragma unroll
            for (int j = 0; j < 4; j++) acc[i][j] = 0.f;

#pragma unroll 8
        for (int c = 0; c < 64; c++) {
            float4 a4 = *(const float4*)&Xi[c * 64 + r4];
            float4 b4 = *(const float4*)&Xj[c * 64 + c4];
            float a[4] = {a4.x, a4.y, a4.z, a4.w};
            float bb[4] = {b4.x, b4.y, b4.z, b4.w};
#pragma unroll
            for (int i = 0; i < 4; i++)
#pragma unroll
                for (int j = 0; j < 4; j++) acc[i][j] += a[i] * bb[j];
        }

#pragma unroll
        for (int i = 0; i < 4; i++) {
            float o = Ob[r4 + i], iz = Zb[r4 + i];
            float4 res;
            res.x = __expf(acc[i][0] - o) * iz;
            res.y = __expf(acc[i][1] - o) * iz;
            res.z = __expf(acc[i][2] - o) * iz;
            res.w = __expf(acc[i][3] - o) * iz;
            *(float4*)(attn + ((size_t)b * KK + k0 + r4 + i) * NN
                       + jslab + jt * 64 + c4) = res;
        }
    }
}

// ---------------------------------------------------------------------------
// Pass 3b: partial sampled over one j-32nd (128 j) — 64 k x 64 c tiles.
// grid (4 ktiles, 32 jo, B) = 512 blocks, 256 threads. attn staged transposed
// so both operands load as LDS.128. Thread: 4x4 register tile.
// ---------------------------------------------------------------------------
__global__ void sampled_kernel(const float* __restrict__ L, const float* __restrict__ attn) {
    __shared__ __align__(16) float XT[64 * 68];   // [jj][c], pad 68
    __shared__ __align__(16) float PtT[64 * 68];  // [jj][k], pad 68
    const int b  = blockIdx.z;
    const int k0 = blockIdx.x * 64;
    const int jbase = blockIdx.y * 128;
    const int t  = threadIdx.x;
    const int k4 = (t & 15) * 4, c4 = (t >> 4) * 4;
    const float* Lb = L + (size_t)b * CC * NN;

    float acc[4][4];
#pragma unroll
    for (int i = 0; i < 4; i++)
#pragma unroll
        for (int j = 0; j < 4; j++) acc[i][j] = 0.f;

    for (int jst = 0; jst < 2; jst++) {
        __syncthreads();
        for (int idx = t; idx < 64 * 64; idx += 256) {
            int c = idx >> 6, jj = idx & 63;
            XT[jj * 68 + c] = Lb[(size_t)c * NN + jbase + jst * 64 + jj];
        }
        for (int idx = t; idx < 64 * 64; idx += 256) {
            int kk = idx >> 6, jj = idx & 63;
            PtT[jj * 68 + kk] =
                attn[((size_t)b * KK + k0 + kk) * NN + jbase + jst * 64 + jj];
        }
        __syncthreads();
#pragma unroll 8
        for (int jj = 0; jj < 64; jj++) {
            float4 p4 = *(const float4*)&PtT[jj * 68 + k4];
            float4 x4 = *(const float4*)&XT[jj * 68 + c4];
            float p[4] = {p4.x, p4.y, p4.z, p4.w};
            float x[4] = {x4.x, x4.y, x4.z, x4.w};
#pragma unroll
            for (int i = 0; i < 4; i++)
#pragma unroll
                for (int j = 0; j < 4; j++) acc[i][j] += p[i] * x[j];
        }
    }
    int q = blockIdx.y;
#pragma unroll
    for (int i = 0; i < 4; i++)
        *(float4*)&g_samp32[q][((size_t)b * KK + k0 + k4 + i) * CC + c4] =
            make_float4(acc[i][0], acc[i][1], acc[i][2], acc[i][3]);
}

// ---------------------------------------------------------------------------
// Pass 4: MLP + L2 normalize, 8 rows per block. 128 blocks x 256 threads.
// ---------------------------------------------------------------------------
__global__ void mlp_kernel(const float* __restrict__ w1, const float* __restrict__ b1,
                           const float* __restrict__ w2, const float* __restrict__ b2,
                           float* __restrict__ emb) {
    __shared__ float s[8 * 64];
    __shared__ float h[8 * 256];
    __shared__ float red[256];
    const int R0 = blockIdx.x * 8;
    const int t = threadIdx.x;

    for (int idx = t; idx < 8 * 64; idx += 256) {
        int r = idx >> 6, c = idx & 63;
        size_t off = (size_t)(R0 + r) * CC + c;
        float acc = 0.f;
#pragma unroll
        for (int q = 0; q < 32; q++) acc += g_samp32[q][off];
        s[r * 64 + c] = acc;
    }
    __syncthreads();

    float a1[8];
#pragma unroll
    for (int r = 0; r < 8; r++) a1[r] = b1[t];
#pragma unroll 4
    for (int c = 0; c < CC; c++) {
        float wv = w1[c * PP + t];
#pragma unroll
        for (int r = 0; r < 8; r++) a1[r] += s[r * 64 + c] * wv;
    }
#pragma unroll
    for (int r = 0; r < 8; r++) h[r * 256 + t] = fmaxf(a1[r], 0.f);
    __syncthreads();

    float a2[8];
#pragma unroll
    for (int r = 0; r < 8; r++) a2[r] = b2[t];
#pragma unroll 4
    for (int p2 = 0; p2 < PP; p2++) {
        float wv = w2[p2 * PP + t];
#pragma unroll
        for (int r = 0; r < 8; r++) a2[r] += h[r * 256 + p2] * wv;
    }

    for (int r = 0; r < 8; r++) {
        red[t] = a2[r] * a2[r];
        __syncthreads();
        for (int sd = 128; sd > 0; sd >>= 1) { if (t < sd) red[t] += red[t + sd]; __syncthreads(); }
        float denom = fmaxf(sqrtf(red[0]), 1e-12f);
        __syncthreads();
        emb[(size_t)(R0 + r) * PP + t] = a2[r] / denom;
    }
}

// ---------------------------------------------------------------------------
extern "C" void kernel_launch(void* const* d_in, const int* in_sizes, int n_in,
                              void* d_out, int out_size) {
    const float* L  = (const float*)d_in[0];
    const float* w1 = (const float*)d_in[1];
    const float* b1 = (const float*)d_in[2];
    const float* w2 = (const float*)d_in[3];
    const float* b2 = (const float*)d_in[4];

    float* out  = (float*)d_out;
    float* emb  = out;                                   // [B,K,P]
    float* attn = out + (size_t)BB * KK * PP;            // [B,K,N]
    float* oidx = attn + (size_t)BB * KK * NN;           // [B,K]

    diag_kernel<<<dim3(4, BB), 1024>>>(L);
    entropy_kernel<<<dim3(NPAIRS, BB), 256>>>(L);
    sort_kernel<<<BB, 1024>>>(L, oidx);
    scores_kernel<<<dim3(4, 32, BB), 256>>>(L, attn);
    sampled_kernel<<<dim3(4, 32, BB), 256>>>(L, attn);
    mlp_kernel<<<128, 256>>>(w1, b1, w2, b2, emb);
}